// round 16
// baseline (speedup 1.0000x reference)
#include <cuda_runtime.h>
#include <cuda_bf16.h>
#include <cstdint>

#define NB 4
#define DIMC 384
#define CC 64
#define GC 3
#define CIN 387
#define NKC 13           /* 13 k-chunks of 32 -> K=416 */

// ---------------- scratch (device globals; no allocation allowed) ----------------
__device__ float d_s2[NB * DIMC * 28 * 28];
__device__ float d_s4[NB * DIMC * 56 * 56];
__device__ float d_s8[NB * DIMC * 112 * 112];
__device__ float d_s16[NB * DIMC * 224 * 224];
__device__ float d_gresA[199920];          // all 4 stages' resized guidance
__device__ float d_comp[NB * CC * 112 * 112];
__device__ float d_wt[NB * 9 * 224 * 224];
// pre-packed bf16-split proj weights: 3 o-tiles x 13 k-chunks x [128m x 32k]
__device__ __align__(16) __nv_bfloat16 d_pwA1[3 * NKC * 4096];
__device__ __align__(16) __nv_bfloat16 d_pwA2[3 * NKC * 4096];
// pre-packed bf16-split comp weights: 4 stages x 13 k-chunks x [64m x 32k]
__device__ __align__(16) __nv_bfloat16 d_cwA1[4 * NKC * 2048];
__device__ __align__(16) __nv_bfloat16 d_cwA2[4 * NKC * 2048];

// stage offsets into d_gresA (NB*GC*h*h each for h = 14,28,56,112)
#define GRES_OFF0 0
#define GRES_OFF1 2352
#define GRES_OFF2 11760
#define GRES_OFF3 49392

// prep kernel work partition
#define PW_N (3 * NKC * 4096)              /* 159744 */
#define CW_N (4 * NKC * 2048)              /* 106496 */
#define RS_N 199920
#define PREP_N (PW_N + CW_N + RS_N)

// ---------------- packed f32x2 helpers ----------------
__device__ __forceinline__ unsigned long long ffma2(unsigned long long a,
                                                    unsigned long long b,
                                                    unsigned long long c) {
    unsigned long long d;
    asm("fma.rn.f32x2 %0, %1, %2, %3;" : "=l"(d) : "l"(a), "l"(b), "l"(c));
    return d;
}
__device__ __forceinline__ unsigned long long pack2(float lo, float hi) {
    unsigned long long d;
    asm("mov.b64 %0, {%1, %2};" : "=l"(d) : "f"(lo), "f"(hi));
    return d;
}
__device__ __forceinline__ unsigned long long dup2(float v) {
    unsigned long long d;
    asm("mov.b64 %0, {%1, %1};" : "=l"(d) : "f"(v));
    return d;
}
__device__ __forceinline__ float lo2(unsigned long long v) {
    return __uint_as_float((unsigned)(v & 0xffffffffull));
}
__device__ __forceinline__ float hi2(unsigned long long v) {
    return __uint_as_float((unsigned)(v >> 32));
}

// ---------------- smem / async helpers ----------------
__device__ __forceinline__ unsigned smem_u32(const void* p) {
    unsigned a;
    asm("{ .reg .u64 t; cvta.to.shared.u64 t, %1; cvt.u32.u64 %0, t; }"
        : "=r"(a) : "l"(p));
    return a;
}
__device__ __forceinline__ void cpasync16(unsigned dst, const void* src) {
    asm volatile("cp.async.ca.shared.global [%0], [%1], 16;"
                 :: "r"(dst), "l"(src));
}
__device__ __forceinline__ void cp_commit() {
    asm volatile("cp.async.commit_group;");
}
template <int N>
__device__ __forceinline__ void cp_wait() {
    asm volatile("cp.async.wait_group %0;" :: "n"(N));
}

// ---------------- mma.sync helpers ----------------
__device__ __forceinline__ void ldsm_x4(uint32_t* r, uint32_t addr) {
    asm volatile("ldmatrix.sync.aligned.m8n8.x4.shared.b16 {%0,%1,%2,%3}, [%4];"
                 : "=r"(r[0]), "=r"(r[1]), "=r"(r[2]), "=r"(r[3]) : "r"(addr));
}
__device__ __forceinline__ void mma_bf16(float* d, const uint32_t* a, const uint32_t* b) {
    asm volatile(
        "mma.sync.aligned.m16n8k16.row.col.f32.bf16.bf16.f32 "
        "{%0,%1,%2,%3}, {%4,%5,%6,%7}, {%8,%9}, {%0,%1,%2,%3};"
        : "+f"(d[0]), "+f"(d[1]), "+f"(d[2]), "+f"(d[3])
        : "r"(a[0]), "r"(a[1]), "r"(a[2]), "r"(a[3]), "r"(b[0]), "r"(b[1]));
}

// split a float into bf16 hi/lo parts
__device__ __forceinline__ void bf16_split(float v, uint32_t& h, uint32_t& l) {
    __nv_bfloat16 hb = __float2bfloat16(v);
    __nv_bfloat16 lb = __float2bfloat16(v - __bfloat162float(hb));
    h = (uint32_t)__bfloat16_as_ushort(hb);
    l = (uint32_t)__bfloat16_as_ushort(lb);
}

// ---------------- fused prep: pack proj weights + pack comp weights + resize ----------------
__global__ void prep_kernel(const float* __restrict__ pw,
                            const float* __restrict__ cw0,
                            const float* __restrict__ cw1,
                            const float* __restrict__ cw2,
                            const float* __restrict__ cw3,
                            const float* __restrict__ g,
                            float* __restrict__ gresA) {
    int idx = blockIdx.x * blockDim.x + threadIdx.x;
    if (idx >= PREP_N) return;
    if (idx < PW_N) {
        // ---- pack proj weights ----
        int k = idx & 31;
        int m = (idx >> 5) & 127;
        int kt = idx >> 12;            // o*NKC + kc
        int o = kt / NKC, kc = kt % NKC;
        int c = kc * 32 + k;
        float w = (c < CIN) ? pw[(size_t)(o * 128 + m) * CIN + c] : 0.f;
        __nv_bfloat16 a1 = __float2bfloat16(w);
        __nv_bfloat16 a2 = __float2bfloat16(w - __bfloat162float(a1));
        int off = kt * 4096 + m * 32 + k;
        d_pwA1[off] = a1;
        d_pwA2[off] = a2;
        return;
    }
    idx -= PW_N;
    if (idx < CW_N) {
        // ---- pack comp weights ----
        int stage = idx / (NKC * 2048);
        int r = idx % (NKC * 2048);
        const float* cw = (stage == 0) ? cw0 : (stage == 1) ? cw1 : (stage == 2) ? cw2 : cw3;
        int k = r & 31;
        int m = (r >> 5) & 63;
        int kc = r >> 11;
        int c = kc * 32 + k;
        float w = (c < CIN) ? cw[(size_t)m * CIN + c] : 0.f;
        __nv_bfloat16 a1 = __float2bfloat16(w);
        __nv_bfloat16 a2 = __float2bfloat16(w - __bfloat162float(a1));
        int off = (stage * NKC + kc) * 2048 + m * 32 + k;
        d_cwA1[off] = a1;
        d_cwA2[off] = a2;
        return;
    }
    idx -= CW_N;
    // ---- bilinear resize (antialias triangle kernel) ----
    int h, off;
    if (idx < GRES_OFF1)      { h = 14;  off = GRES_OFF0; }
    else if (idx < GRES_OFF2) { h = 28;  off = GRES_OFF1; }
    else if (idx < GRES_OFF3) { h = 56;  off = GRES_OFF2; }
    else                      { h = 112; off = GRES_OFF3; }
    int r = idx - off;
    int j = r % h;
    int t = r / h;
    int i = t % h;
    int bc = t / h;
    float scale = (float)h / 224.0f;
    float inv = 224.0f / (float)h;
    float si = (i + 0.5f) * inv - 0.5f;
    float sj = (j + 0.5f) * inv - 0.5f;
    int i0 = max(0, (int)floorf(si - inv) + 1);
    int i1 = min(223, (int)ceilf(si + inv) - 1);
    int j0 = max(0, (int)floorf(sj - inv) + 1);
    int j1 = min(223, (int)ceilf(sj + inv) - 1);
    const float* gp = g + (size_t)bc * 224 * 224;
    float wj_sum = 0.f;
    for (int jj = j0; jj <= j1; ++jj)
        wj_sum += fmaxf(0.f, 1.f - fabsf((float)jj - sj) * scale);
    float wi_sum = 0.f, acc = 0.f;
    for (int ii = i0; ii <= i1; ++ii) {
        float wi = fmaxf(0.f, 1.f - fabsf((float)ii - si) * scale);
        wi_sum += wi;
        if (wi > 0.f) {
            float row = 0.f;
            const float* rp = gp + ii * 224;
            for (int jj = j0; jj <= j1; ++jj) {
                float wj = fmaxf(0.f, 1.f - fabsf((float)jj - sj) * scale);
                row += wj * rp[jj];
            }
            acc += wi * row;
        }
    }
    gresA[idx] = acc / (wi_sum * wj_sum);
}

// ---------------- comp: 1x1 conv 387 -> 64 as bf16-split mma GEMM ----------------
#define ROWB 80
#define CSTAGE 30720
#define CSMEM (2 * CSTAGE)
__global__ __launch_bounds__(256, 2) void comp_mma_kernel(const float* __restrict__ src,
                                                          const float* __restrict__ gres,
                                                          const float* __restrict__ cb,
                                                          float* __restrict__ comp,
                                                          int hw, int stage) {
    extern __shared__ char smem[];
    const uint32_t sb = smem_u32(smem);
    const int tid = threadIdx.x;
    const int wid = tid >> 5, lane = tid & 31;
    const int wm = wid >> 2, wn = wid & 3;          // warp grid 2 x 4 (M 32 each, N 32)
    const int b = blockIdx.y;
    const int p0 = blockIdx.x * 128;

    float acc[2][4][4];
#pragma unroll
    for (int mf = 0; mf < 2; ++mf)
#pragma unroll
        for (int nf = 0; nf < 4; ++nf)
#pragma unroll
            for (int r = 0; r < 4; ++r) acc[mf][nf][r] = 0.f;

    const int cq = tid & 7, pg = tid >> 3;
    const int c0l = 4 * cq, px0 = pg * 4;

    const int a_row_l = lane & 15;
    const int a_kadd = (lane >> 4) << 4;
    const int b_row_l = (lane & 7) | ((lane & 16) >> 1);
    const int b_kadd = (lane & 8) << 1;

    auto chanp = [&](int c) -> const float* {
        if (c < DIMC) return src + ((size_t)b * DIMC + c) * hw + p0;
        if (c < CIN) return gres + ((size_t)b * GC + (c - DIMC)) * hw + p0;
        return (const float*)0;
    };

    auto a_issue = [&](int kc, int s) {
        const __nv_bfloat16* g1 = d_cwA1 + (size_t)(stage * NKC + kc) * 2048;
        const __nv_bfloat16* g2 = d_cwA2 + (size_t)(stage * NKC + kc) * 2048;
        uint32_t d1 = sb + s * CSTAGE;
        uint32_t d2 = d1 + 5120;
        int row = tid >> 2, sg = tid & 3;
        cpasync16(d1 + row * ROWB + sg * 16, g1 + row * 32 + sg * 8);
        cpasync16(d2 + row * ROWB + sg * 16, g2 + row * 32 + sg * 8);
        cp_commit();
    };
    float4 bq[4];
    auto b_issue = [&](int kc) {
        float4 z = make_float4(0.f, 0.f, 0.f, 0.f);
        bool inb = (p0 + px0) < hw;
#pragma unroll
        for (int u = 0; u < 4; ++u) {
            const float* r = chanp(kc * 32 + c0l + u);
            bq[u] = (r && inb) ? __ldg((const float4*)(r + px0)) : z;
        }
    };
    auto b_store = [&](int s) {
        uint32_t b1 = sb + s * CSTAGE + 10240;
        uint32_t b2 = b1 + 10240;
#pragma unroll
        for (int i = 0; i < 4; ++i) {
            uint32_t h[4], l[4];
#pragma unroll
            for (int u = 0; u < 4; ++u)
                bf16_split(((const float*)&bq[u])[i], h[u], l[u]);
            uint32_t hp0 = h[0] | (h[1] << 16), hp1 = h[2] | (h[3] << 16);
            uint32_t lp0 = l[0] | (l[1] << 16), lp1 = l[2] | (l[3] << 16);
            uint32_t off = (uint32_t)(px0 + i) * ROWB + c0l * 2;
            asm volatile("st.shared.v2.b32 [%0], {%1, %2};"
                         :: "r"(b1 + off), "r"(hp0), "r"(hp1) : "memory");
            asm volatile("st.shared.v2.b32 [%0], {%1, %2};"
                         :: "r"(b2 + off), "r"(lp0), "r"(lp1) : "memory");
        }
    };

    a_issue(0, 0);
    b_issue(0);
    b_store(0);
    cp_wait<0>();
    __syncthreads();

    for (int kc = 0; kc < NKC; ++kc) {
        int s = kc & 1;
        if (kc + 1 < NKC) {
            a_issue(kc + 1, s ^ 1);
            b_issue(kc + 1);
        }
        uint32_t A1b = sb + s * CSTAGE;
        uint32_t A2b = A1b + 5120;
        uint32_t B1b = A1b + 10240;
        uint32_t B2b = A1b + 20480;
#pragma unroll
        for (int ks = 0; ks < 2; ++ks) {
            uint32_t koff = ks * 32;
            uint32_t aoff = (uint32_t)(wm * 32 + a_row_l) * ROWB + koff + a_kadd;
            uint32_t boff0 = (uint32_t)(wn * 32 + b_row_l) * ROWB + koff + b_kadd;
            uint32_t boff1 = boff0 + 16 * ROWB;
            uint32_t av[8], bv1[8], bv2[8];
            ldsm_x4(bv1, B1b + boff0);
            ldsm_x4(bv1 + 4, B1b + boff1);
#pragma unroll
            for (int mf = 0; mf < 2; ++mf)
                ldsm_x4(av + mf * 4, A1b + aoff + mf * 16 * ROWB);
#pragma unroll
            for (int mf = 0; mf < 2; ++mf)
#pragma unroll
                for (int nf = 0; nf < 4; ++nf)
                    mma_bf16(acc[mf][nf], av + mf * 4, bv1 + nf * 2);
            ldsm_x4(bv2, B2b + boff0);
            ldsm_x4(bv2 + 4, B2b + boff1);
#pragma unroll
            for (int mf = 0; mf < 2; ++mf)
#pragma unroll
                for (int nf = 0; nf < 4; ++nf)
                    mma_bf16(acc[mf][nf], av + mf * 4, bv2 + nf * 2);
#pragma unroll
            for (int mf = 0; mf < 2; ++mf)
                ldsm_x4(av + mf * 4, A2b + aoff + mf * 16 * ROWB);
#pragma unroll
            for (int mf = 0; mf < 2; ++mf)
#pragma unroll
                for (int nf = 0; nf < 4; ++nf)
                    mma_bf16(acc[mf][nf], av + mf * 4, bv1 + nf * 2);
        }
        if (kc + 1 < NKC) {
            b_store(s ^ 1);
            cp_wait<0>();
        }
        __syncthreads();
    }

#pragma unroll
    for (int mf = 0; mf < 2; ++mf) {
        int row0 = wm * 32 + mf * 16 + (lane >> 2);
        int row1 = row0 + 8;
        float bias0 = __ldg(&cb[row0]);
        float bias1 = __ldg(&cb[row1]);
        float* ob0 = comp + ((size_t)b * CC + row0) * hw;
        float* ob1 = comp + ((size_t)b * CC + row1) * hw;
        int colb = wn * 32 + (lane & 3) * 2;
#pragma unroll
        for (int nf = 0; nf < 4; ++nf) {
            int col = p0 + colb + nf * 8;
            if (col < hw) {
                *(float2*)(ob0 + col) = make_float2(acc[mf][nf][0] + bias0,
                                                    acc[mf][nf][1] + bias0);
                *(float2*)(ob1 + col) = make_float2(acc[mf][nf][2] + bias1,
                                                    acc[mf][nf][3] + bias1);
            }
        }
    }
}

// ---------------- mask + softmax + pixel-shuffle fused ----------------
__global__ __launch_bounds__(256) void mask_kernel(const float* __restrict__ comp,
                                                   const float* __restrict__ ew,
                                                   const float* __restrict__ eb,
                                                   float* __restrict__ wt, int h) {
    extern __shared__ float sE[]; // [CC][9][36]
    int tid = threadIdx.x;
    for (int i = tid; i < CC * 9 * 36; i += 256) {
        int m = i % 36;
        int ck = i / 36;
        int k = ck % 9;
        int c = ck / 9;
        sE[i] = ew[(m * CC + c) * 9 + k];
    }
    __syncthreads();
    int hw = h * h;
    int pix = blockIdx.x * 256 + tid;
    int b = blockIdx.y;
    if (pix >= hw) return;
    int i = pix / h, j = pix % h;

    unsigned long long acc[18];
#pragma unroll
    for (int p = 0; p < 18; ++p)
        acc[p] = pack2(__ldg(&eb[2 * p]), __ldg(&eb[2 * p + 1]));

    int offs[9];
    bool val[9];
#pragma unroll
    for (int k = 0; k < 9; ++k) {
        int di = k / 3 - 1, dj = k % 3 - 1;
        int ii = i + di, jj = j + dj;
        val[k] = (ii >= 0) && (ii < h) && (jj >= 0) && (jj < h);
        offs[k] = val[k] ? (ii * h + jj) : 0;
    }
    const float* cp = comp + (size_t)b * CC * hw;
#pragma unroll 1
    for (int c0 = 0; c0 < CC; c0 += 4) {
        float v4[4][9];
#pragma unroll
        for (int u = 0; u < 4; ++u) {
            const float* cpu = cp + (size_t)(c0 + u) * hw;
#pragma unroll
            for (int k = 0; k < 9; ++k)
                v4[u][k] = val[k] ? cpu[offs[k]] : 0.f;
        }
#pragma unroll
        for (int u = 0; u < 4; ++u) {
#pragma unroll
            for (int k = 0; k < 9; ++k) {
                unsigned long long vv = dup2(v4[u][k]);
                const ulonglong2* w2 = (const ulonglong2*)&sE[((c0 + u) * 9 + k) * 36];
#pragma unroll
                for (int q = 0; q < 9; ++q) {
                    ulonglong2 w = w2[q];
                    acc[2 * q] = ffma2(vv, w.x, acc[2 * q]);
                    acc[2 * q + 1] = ffma2(vv, w.y, acc[2 * q + 1]);
                }
            }
        }
    }
    // fused softmax over the 9 taps of each quad member pq (channel c = 4k + pq)
    float vals[4][9];
#pragma unroll
    for (int pq = 0; pq < 4; ++pq) {
#pragma unroll
        for (int k = 0; k < 9; ++k) {
            int c = 4 * k + pq;
            vals[pq][k] = (c & 1) ? hi2(acc[c >> 1]) : lo2(acc[c >> 1]);
        }
        float mx = -1e30f;
#pragma unroll
        for (int k = 0; k < 9; ++k) mx = fmaxf(mx, vals[pq][k]);
        float s = 0.f;
#pragma unroll
        for (int k = 0; k < 9; ++k) {
            vals[pq][k] = __expf(vals[pq][k] - mx);
            s += vals[pq][k];
        }
        float inv = 1.f / s;
#pragma unroll
        for (int k = 0; k < 9; ++k) vals[pq][k] *= inv;
    }
    float* wp = wt + (((size_t)b * 9) * hw + pix) * 4;
#pragma unroll
    for (int k = 0; k < 9; ++k)
        *(float4*)(wp + (size_t)k * hw * 4) =
            make_float4(vals[0][k], vals[1][k], vals[2][k], vals[3][k]);
}

// ---------------- CARAFE reassembly: double-buffered xs, ONE sync per chunk ----------------
#define CARAFE_CH 8
#define CARAFE_NE (CARAFE_CH * 324)  // 18x18 window per channel
__global__ __launch_bounds__(256) void carafe_kernel(const float* __restrict__ src,
                                                     const float* __restrict__ wt,
                                                     float* __restrict__ out, int h) {
    int H = 2 * h, hw = h * h, HW = H * H;
    int b = blockIdx.z;
    int i0 = blockIdx.y * 16;
    int j0 = blockIdx.x * 16;
    int tid = threadIdx.x;
    int ti = tid >> 4, tj = tid & 15;
    int i = i0 + ti, j = j0 + tj;
    bool valid = (i < h) && (j < h);
    __shared__ float xs[2][CARAFE_CH][18][18];

    float4 w4[9];
    {
        const float4* wb = (const float4*)(wt + (((size_t)b * 9) * hw + i * h + j) * 4);
#pragma unroll
        for (int k = 0; k < 9; ++k)
            w4[k] = valid ? wb[(size_t)k * hw] : make_float4(0.f, 0.f, 0.f, 0.f);
    }

    int loff[11], sflat[11];
    bool vld[11];
    int cnt = 0;
    for (int e = tid; e < CARAFE_NE; e += 256) {
        int c = e / 324;
        int r = e % 324;
        int ii = r / 18, jj = r % 18;
        int gi = i0 - 1 + ii, gj = j0 - 1 + jj;
        bool v = (gi >= 0) && (gi < h) && (gj >= 0) && (gj < h);
        loff[cnt] = c * hw + (v ? (gi * h + gj) : 0);
        sflat[cnt] = e;
        vld[cnt] = v;
        cnt++;
    }
    const float* sb = src + (size_t)b * DIMC * hw;
    float* ob = out + (size_t)b * DIMC * HW;
    float rv[11];
#pragma unroll
    for (int q = 0; q < 11; ++q)
        rv[q] = (q < cnt && vld[q]) ? __ldg(sb + loff[q]) : 0.f;

    int I = 2 * i, J = 2 * j;
    int it = 0;
    for (int cc = 0; cc < DIMC; cc += CARAFE_CH, ++it) {
        int buf = it & 1;
        float* xsf = &xs[buf][0][0][0];
        // write current chunk (safe: xs[buf] last computed-from at iter it-2,
        // whose compute finished before iter it-1's barrier)
#pragma unroll
        for (int q = 0; q < 11; ++q)
            if (q < cnt) xsf[sflat[q]] = rv[q];
        __syncthreads();
        // prefetch next chunk while computing this one
        if (cc + CARAFE_CH < DIMC) {
            const float* sbc = sb + (size_t)(cc + CARAFE_CH) * hw;
#pragma unroll
            for (int q = 0; q < 11; ++q)
                rv[q] = (q < cnt && vld[q]) ? __ldg(sbc + loff[q]) : 0.f;
        }
#pragma unroll
        for (int c = 0; c < CARAFE_CH; ++c) {
            float a00 = 0.f, a01 = 0.f, a10 = 0.f, a11 = 0.f;
#pragma unroll
            for (int k = 0; k < 9; ++k) {
                float x = xs[buf][c][ti + k / 3][tj + k % 3];
                a00 += w4[k].x * x;
                a01 += w4[k].y * x;
                a10 += w4[k].z * x;
                a11 += w4[k].w * x;
            }
            if (valid) {
                float* o0 = ob + (size_t)(cc + c) * HW + (size_t)I * H + J;
                *(float2*)o0 = make_float2(a00, a01);
                *(float2*)(o0 + H) = make_float2(a10, a11);
            }
        }
    }
}

// ---------------- final 1x1 conv: mma.sync bf16-split (3-term) GEMM ----------------
// BM=128 (out ch), BN=128 (px), BK=32, K=416; warp grid 2x4, mf=4, nf=4.
// Stage: A1(10240) A2(10240) B1(10240) B2(10240) = 40960; 2 stages -> 2 CTA/SM.
#define STAGE_SZ 40960
#define PJ_SMEM (2 * STAGE_SZ)
__global__ __launch_bounds__(256, 2) void proj_mma_kernel(const float* __restrict__ s16,
                                                          const float* __restrict__ guid,
                                                          const float* __restrict__ pb,
                                                          float* __restrict__ out) {
    extern __shared__ char smem[];
    const uint32_t sb = smem_u32(smem);
    const int tid = threadIdx.x;
    const int wid = tid >> 5, lane = tid & 31;
    const int wm = wid >> 2, wn = wid & 3;          // warp grid 2 x 4
    const int pt = blockIdx.x, ot = blockIdx.y, b = blockIdx.z;
    const size_t NPIX = 50176;
    const size_t p0 = (size_t)pt * 128;
    const int o0 = ot * 128;

    float acc[4][4][4];
#pragma unroll
    for (int mf = 0; mf < 4; ++mf)
#pragma unroll
        for (int nf = 0; nf < 4; ++nf)
#pragma unroll
            for (int r = 0; r < 4; ++r) acc[mf][nf][r] = 0.f;

    // B fill: channel quad cq (4 ch), pixel group pg (4 px)
    const int cq = tid & 7, pg = tid >> 3;
    const int c0l = 4 * cq, px0 = pg * 4;

    const int a_row_l = lane & 15;
    const int a_kadd = (lane >> 4) << 4;
    const int b_row_l = (lane & 7) | ((lane & 16) >> 1);
    const int b_kadd = (lane & 8) << 1;

    auto chanp = [&](int c) -> const float* {
        if (c < DIMC) return s16 + ((size_t)(b * DIMC + c)) * NPIX + p0;
        if (c < CIN) return guid + ((size_t)(b * GC + (c - DIMC))) * NPIX + p0;
        return (const float*)0;
    };

    auto a_issue = [&](int kc, int s) {
        const __nv_bfloat16* g1 = d_pwA1 + (ot * NKC + kc) * 4096;
        const __nv_bfloat16* g2 = d_pwA2 + (ot * NKC + kc) * 4096;
        uint32_t d1 = sb + s * STAGE_SZ;
        uint32_t d2 = d1 + 10240;
#pragma unroll
        for (int r = 0; r < 2; ++r) {
            int seg = tid + r * 256;           // 512 segments of 16B
            int row = seg >> 2, sg = seg & 3;
            cpasync16(d1 + row * ROWB + sg * 16, g1 + row * 32 + sg * 8);
            cpasync16(d2 + row * ROWB + sg * 16, g2 + row * 32 + sg * 8);
        }
        cp_commit();
    };
    float4 bq[4];
    auto b_issue = [&](int kc) {
        float4 z = make_float4(0.f, 0.f, 0.f, 0.f);
#pragma unroll
        for (int u = 0; u < 4; ++u) {
            const float* r = chanp(kc * 32 + c0l + u);
            bq[u] = r ? __ldg((const float4*)(r + px0)) : z;
        }
    };
    auto b_store = [&](int s) {
        uint32_t b1 = sb + s * STAGE_SZ + 20480;
        uint32_t b2 = b1 + 10240;
#pragma unroll
        for (int i = 0; i < 4; ++i) {
            uint32_t h[4], l[4];
#pragma unroll
            for (int u = 0; u < 4; ++u)
                bf16_split(((const float*)&bq[u])[i], h[u], l[u]);
            uint32_t hp0 = h[0] | (h[1] << 16), hp1 = h[2] | (h[3] << 16);
            uint32_t lp0 = l[0] | (l[1] << 16), lp1 = l[2] | (l[3] << 16);
            uint32_t off = (uint32_t)(px0 + i) * ROWB + c0l * 2;
            asm volatile("st.shared.v2.b32 [%0], {%1, %2};"
                         :: "r"(b1 + off), "r"(hp0), "r"(hp1) : "memory");
            asm volatile("st.shared.v2.b32 [%0], {%1, %2};"
                         :: "r"(b2 + off), "r"(lp0), "r"(lp1) : "memory");
        }
    };

    // prefill chunk 0
    a_issue(0, 0);
    b_issue(0);
    b_store(0);
    cp_wait<0>();
    __syncthreads();

    for (int kc = 0; kc < NKC; ++kc) {
        int s = kc & 1;
        if (kc + 1 < NKC) {
            a_issue(kc + 1, s ^ 1);   // async
            b_issue(kc + 1);          // LDGs in flight during compute
        }
        uint32_t A1b = sb + s * STAGE_SZ;
        uint32_t A2b = A1b + 10240;
        uint32_t B1b = A1b + 20480;
        uint32_t B2b = A1b + 30720;
#pragma unroll
        for (int ks = 0; ks < 2; ++ks) {
            uint32_t koff = ks * 32;
            uint32_t aoff = (uint32_t)(wm * 64 + a_row_l) * ROWB + koff + a_kadd;
            uint32_t boff0 = (uint32_t)(wn * 32 + b_row_l) * ROWB + koff + b_kadd;
            uint32_t boff1 = boff0 + 16 * ROWB;
            uint32_t av[16], bv1[8], bv2[8];
            ldsm_x4(bv1, B1b + boff0);
            ldsm_x4(bv1 + 4, B1b + boff1);
#pragma unroll
            for (int mf = 0; mf < 4; ++mf)
                ldsm_x4(av + mf * 4, A1b + aoff + mf * 16 * ROWB);
#pragma unroll
            for (int mf = 0; mf < 4; ++mf)
#pragma unroll
                for (int nf = 0; nf < 4; ++nf)
                    mma_bf16(acc[mf][nf], av + mf * 4, bv1 + nf * 2);
            ldsm_x4(bv2, B2b + boff0);
            ldsm_x4(bv2 + 4, B2b + boff1);
#pragma unroll
            for (int mf = 0; mf < 4; ++mf)
#pragma unroll
                for (int nf = 0; nf < 4; ++nf)
                    mma_bf16(acc[mf][nf], av + mf * 4, bv2 + nf * 2);
#pragma unroll
            for (int mf = 0; mf < 4; ++mf)
                ldsm_x4(av + mf * 4, A2b + aoff + mf * 16 * ROWB);
#pragma unroll
            for (int mf = 0; mf < 4; ++mf)
#pragma unroll
                for (int nf = 0; nf < 4; ++nf)
                    mma_bf16(acc[mf][nf], av + mf * 4, bv1 + nf * 2);
        }
        if (kc + 1 < NKC) {
            b_store(s ^ 1);
            cp_wait<0>();
        }
        __syncthreads();
    }

    // ---- epilogue ----
#pragma unroll
    for (int mf = 0; mf < 4; ++mf) {
        int row0 = o0 + wm * 64 + mf * 16 + (lane >> 2);
        int row1 = row0 + 8;
        float bias0 = __ldg(&pb[row0]);
        float bias1 = __ldg(&pb[row1]);
        float* ob0 = out + ((size_t)(b * DIMC + row0)) * NPIX + p0 + wn * 32 + (lane & 3) * 2;
        float* ob1 = out + ((size_t)(b * DIMC + row1)) * NPIX + p0 + wn * 32 + (lane & 3) * 2;
#pragma unroll
        for (int nf = 0; nf < 4; ++nf) {
            *(float2*)(ob0 + nf * 8) = make_float2(acc[mf][nf][0] + bias0,
                                                   acc[mf][nf][1] + bias0);
            *(float2*)(ob1 + nf * 8) = make_float2(acc[mf][nf][2] + bias1,
                                                   acc[mf][nf][3] + bias1);
        }
    }
}

// ---------------- driver ----------------
extern "C" void kernel_launch(void* const* d_in, const int* in_sizes, int n_in,
                              void* d_out, int out_size) {
    (void)in_sizes; (void)n_in; (void)out_size;
    const float* source = (const float*)d_in[0];
    const float* guid = (const float*)d_in[1];
    const float* proj_w = (const float*)d_in[18];
    const float* proj_b = (const float*)d_in[19];

    float *s2, *s4, *s8, *s16, *gresA, *comp, *wtb;
    cudaGetSymbolAddress((void**)&s2, d_s2);
    cudaGetSymbolAddress((void**)&s4, d_s4);
    cudaGetSymbolAddress((void**)&s8, d_s8);
    cudaGetSymbolAddress((void**)&s16, d_s16);
    cudaGetSymbolAddress((void**)&gresA, d_gresA);
    cudaGetSymbolAddress((void**)&comp, d_comp);
    cudaGetSymbolAddress((void**)&wtb, d_wt);

    cudaFuncSetAttribute(mask_kernel, cudaFuncAttributeMaxDynamicSharedMemorySize,
                         CC * 9 * 36 * 4);
    cudaFuncSetAttribute(comp_mma_kernel, cudaFuncAttributeMaxDynamicSharedMemorySize,
                         CSMEM);
    cudaFuncSetAttribute(proj_mma_kernel, cudaFuncAttributeMaxDynamicSharedMemorySize,
                         PJ_SMEM);

    // fused prep: proj weight pack + comp weight packs + all resizes
    prep_kernel<<<(PREP_N + 255) / 256, 256>>>(
        proj_w, (const float*)d_in[2], (const float*)d_in[6],
        (const float*)d_in[10], (const float*)d_in[14], guid, gresA);

    const float* cur = source;
    float* outs[4] = {s2, s4, s8, s16};
    const int hs[4] = {14, 28, 56, 112};
    const int goff[4] = {GRES_OFF0, GRES_OFF1, GRES_OFF2, GRES_OFF3};
    for (int s = 0; s < 4; ++s) {
        int h = hs[s], hw = h * h;
        const float* cb = (const float*)d_in[3 + 4 * s];
        const float* ew = (const float*)d_in[4 + 4 * s];
        const float* eb = (const float*)d_in[5 + 4 * s];
        comp_mma_kernel<<<dim3((hw + 127) / 128, NB), 256, CSMEM>>>(cur, gresA + goff[s],
                                                                    cb, comp, hw, s);
        mask_kernel<<<dim3((hw + 255) / 256, NB), 256, CC * 9 * 36 * 4>>>(comp, ew, eb,
                                                                          wtb, h);
        int nt = (h + 15) / 16;
        carafe_kernel<<<dim3(nt, nt, NB), 256>>>(cur, wtb, outs[s], h);
        cur = outs[s];
    }
    proj_mma_kernel<<<dim3(392, 3, NB), 256, PJ_SMEM>>>(s16, guid, proj_b, (float*)d_out);
}

// round 17
// speedup vs baseline: 1.1286x; 1.1286x over previous
#include <cuda_runtime.h>
#include <cuda_bf16.h>
#include <cstdint>

#define NB 4
#define DIMC 384
#define CC 64
#define GC 3
#define CIN 387
#define NKC 13           /* 13 k-chunks of 32 -> K=416 */

// ---------------- scratch (device globals; no allocation allowed) ----------------
__device__ float d_s2[NB * DIMC * 28 * 28];
__device__ float d_s4[NB * DIMC * 56 * 56];
__device__ float d_s8[NB * DIMC * 112 * 112];
__device__ float d_s16[NB * DIMC * 224 * 224];
__device__ float d_gresA[199920];          // all 4 stages' resized guidance
__device__ float d_comp[NB * CC * 112 * 112];
__device__ float d_wt[NB * 9 * 224 * 224];
// pre-packed bf16-split proj weights: 3 o-tiles x 13 k-chunks x [128m x 32k]
__device__ __align__(16) __nv_bfloat16 d_pwA1[3 * NKC * 4096];
__device__ __align__(16) __nv_bfloat16 d_pwA2[3 * NKC * 4096];
// pre-packed bf16-split comp weights: 4 stages x 13 k-chunks x [64m x 32k]
__device__ __align__(16) __nv_bfloat16 d_cwA1[4 * NKC * 2048];
__device__ __align__(16) __nv_bfloat16 d_cwA2[4 * NKC * 2048];

// stage offsets into d_gresA (NB*GC*h*h each for h = 14,28,56,112)
#define GRES_OFF0 0
#define GRES_OFF1 2352
#define GRES_OFF2 11760
#define GRES_OFF3 49392

// prep kernel work partition
#define PW_N (3 * NKC * 4096)              /* 159744 */
#define CW_N (4 * NKC * 2048)              /* 106496 */
#define RS_N 199920
#define PREP_N (PW_N + CW_N + RS_N)

// ---------------- packed f32x2 helpers ----------------
__device__ __forceinline__ unsigned long long ffma2(unsigned long long a,
                                                    unsigned long long b,
                                                    unsigned long long c) {
    unsigned long long d;
    asm("fma.rn.f32x2 %0, %1, %2, %3;" : "=l"(d) : "l"(a), "l"(b), "l"(c));
    return d;
}
__device__ __forceinline__ unsigned long long pack2(float lo, float hi) {
    unsigned long long d;
    asm("mov.b64 %0, {%1, %2};" : "=l"(d) : "f"(lo), "f"(hi));
    return d;
}
__device__ __forceinline__ unsigned long long dup2(float v) {
    unsigned long long d;
    asm("mov.b64 %0, {%1, %1};" : "=l"(d) : "f"(v));
    return d;
}
__device__ __forceinline__ float lo2(unsigned long long v) {
    return __uint_as_float((unsigned)(v & 0xffffffffull));
}
__device__ __forceinline__ float hi2(unsigned long long v) {
    return __uint_as_float((unsigned)(v >> 32));
}

// ---------------- smem / async helpers ----------------
__device__ __forceinline__ unsigned smem_u32(const void* p) {
    unsigned a;
    asm("{ .reg .u64 t; cvta.to.shared.u64 t, %1; cvt.u32.u64 %0, t; }"
        : "=r"(a) : "l"(p));
    return a;
}
__device__ __forceinline__ void cpasync16(unsigned dst, const void* src) {
    asm volatile("cp.async.ca.shared.global [%0], [%1], 16;"
                 :: "r"(dst), "l"(src));
}
__device__ __forceinline__ void cp_commit() {
    asm volatile("cp.async.commit_group;");
}
template <int N>
__device__ __forceinline__ void cp_wait() {
    asm volatile("cp.async.wait_group %0;" :: "n"(N));
}

// ---------------- mma.sync helpers ----------------
__device__ __forceinline__ void ldsm_x4(uint32_t* r, uint32_t addr) {
    asm volatile("ldmatrix.sync.aligned.m8n8.x4.shared.b16 {%0,%1,%2,%3}, [%4];"
                 : "=r"(r[0]), "=r"(r[1]), "=r"(r[2]), "=r"(r[3]) : "r"(addr));
}
__device__ __forceinline__ void mma_bf16(float* d, const uint32_t* a, const uint32_t* b) {
    asm volatile(
        "mma.sync.aligned.m16n8k16.row.col.f32.bf16.bf16.f32 "
        "{%0,%1,%2,%3}, {%4,%5,%6,%7}, {%8,%9}, {%0,%1,%2,%3};"
        : "+f"(d[0]), "+f"(d[1]), "+f"(d[2]), "+f"(d[3])
        : "r"(a[0]), "r"(a[1]), "r"(a[2]), "r"(a[3]), "r"(b[0]), "r"(b[1]));
}

// split a float into bf16 hi/lo parts
__device__ __forceinline__ void bf16_split(float v, uint32_t& h, uint32_t& l) {
    __nv_bfloat16 hb = __float2bfloat16(v);
    __nv_bfloat16 lb = __float2bfloat16(v - __bfloat162float(hb));
    h = (uint32_t)__bfloat16_as_ushort(hb);
    l = (uint32_t)__bfloat16_as_ushort(lb);
}

// ---------------- fused prep: pack proj weights + pack comp weights + resize ----------------
__global__ void prep_kernel(const float* __restrict__ pw,
                            const float* __restrict__ cw0,
                            const float* __restrict__ cw1,
                            const float* __restrict__ cw2,
                            const float* __restrict__ cw3,
                            const float* __restrict__ g,
                            float* __restrict__ gresA) {
    int idx = blockIdx.x * blockDim.x + threadIdx.x;
    if (idx >= PREP_N) return;
    if (idx < PW_N) {
        int k = idx & 31;
        int m = (idx >> 5) & 127;
        int kt = idx >> 12;            // o*NKC + kc
        int o = kt / NKC, kc = kt % NKC;
        int c = kc * 32 + k;
        float w = (c < CIN) ? pw[(size_t)(o * 128 + m) * CIN + c] : 0.f;
        __nv_bfloat16 a1 = __float2bfloat16(w);
        __nv_bfloat16 a2 = __float2bfloat16(w - __bfloat162float(a1));
        int off = kt * 4096 + m * 32 + k;
        d_pwA1[off] = a1;
        d_pwA2[off] = a2;
        return;
    }
    idx -= PW_N;
    if (idx < CW_N) {
        int stage = idx / (NKC * 2048);
        int r = idx % (NKC * 2048);
        const float* cw = (stage == 0) ? cw0 : (stage == 1) ? cw1 : (stage == 2) ? cw2 : cw3;
        int k = r & 31;
        int m = (r >> 5) & 63;
        int kc = r >> 11;
        int c = kc * 32 + k;
        float w = (c < CIN) ? cw[(size_t)m * CIN + c] : 0.f;
        __nv_bfloat16 a1 = __float2bfloat16(w);
        __nv_bfloat16 a2 = __float2bfloat16(w - __bfloat162float(a1));
        int off = (stage * NKC + kc) * 2048 + m * 32 + k;
        d_cwA1[off] = a1;
        d_cwA2[off] = a2;
        return;
    }
    idx -= CW_N;
    int h, off;
    if (idx < GRES_OFF1)      { h = 14;  off = GRES_OFF0; }
    else if (idx < GRES_OFF2) { h = 28;  off = GRES_OFF1; }
    else if (idx < GRES_OFF3) { h = 56;  off = GRES_OFF2; }
    else                      { h = 112; off = GRES_OFF3; }
    int r = idx - off;
    int j = r % h;
    int t = r / h;
    int i = t % h;
    int bc = t / h;
    float scale = (float)h / 224.0f;
    float inv = 224.0f / (float)h;
    float si = (i + 0.5f) * inv - 0.5f;
    float sj = (j + 0.5f) * inv - 0.5f;
    int i0 = max(0, (int)floorf(si - inv) + 1);
    int i1 = min(223, (int)ceilf(si + inv) - 1);
    int j0 = max(0, (int)floorf(sj - inv) + 1);
    int j1 = min(223, (int)ceilf(sj + inv) - 1);
    const float* gp = g + (size_t)bc * 224 * 224;
    float wj_sum = 0.f;
    for (int jj = j0; jj <= j1; ++jj)
        wj_sum += fmaxf(0.f, 1.f - fabsf((float)jj - sj) * scale);
    float wi_sum = 0.f, acc = 0.f;
    for (int ii = i0; ii <= i1; ++ii) {
        float wi = fmaxf(0.f, 1.f - fabsf((float)ii - si) * scale);
        wi_sum += wi;
        if (wi > 0.f) {
            float row = 0.f;
            const float* rp = gp + ii * 224;
            for (int jj = j0; jj <= j1; ++jj) {
                float wj = fmaxf(0.f, 1.f - fabsf((float)jj - sj) * scale);
                row += wj * rp[jj];
            }
            acc += wi * row;
        }
    }
    gresA[idx] = acc / (wi_sum * wj_sum);
}

// ---------------- comp: 1x1 conv 387 -> 64 as bf16-split mma GEMM ----------------
#define ROWB 80
#define CSTAGE 30720
#define CSMEM (2 * CSTAGE)
__global__ __launch_bounds__(256, 2) void comp_mma_kernel(const float* __restrict__ src,
                                                          const float* __restrict__ gres,
                                                          const float* __restrict__ cb,
                                                          float* __restrict__ comp,
                                                          int hw, int stage) {
    extern __shared__ char smem[];
    const uint32_t sb = smem_u32(smem);
    const int tid = threadIdx.x;
    const int wid = tid >> 5, lane = tid & 31;
    const int wm = wid >> 2, wn = wid & 3;          // warp grid 2 x 4 (M 32 each, N 32)
    const int b = blockIdx.y;
    const int p0 = blockIdx.x * 128;

    float acc[2][4][4];
#pragma unroll
    for (int mf = 0; mf < 2; ++mf)
#pragma unroll
        for (int nf = 0; nf < 4; ++nf)
#pragma unroll
            for (int r = 0; r < 4; ++r) acc[mf][nf][r] = 0.f;

    const int cq = tid & 7, pg = tid >> 3;
    const int c0l = 4 * cq, px0 = pg * 4;

    const int a_row_l = lane & 15;
    const int a_kadd = (lane >> 4) << 4;
    const int b_row_l = (lane & 7) | ((lane & 16) >> 1);
    const int b_kadd = (lane & 8) << 1;

    auto chanp = [&](int c) -> const float* {
        if (c < DIMC) return src + ((size_t)b * DIMC + c) * hw + p0;
        if (c < CIN) return gres + ((size_t)b * GC + (c - DIMC)) * hw + p0;
        return (const float*)0;
    };

    auto a_issue = [&](int kc, int s) {
        const __nv_bfloat16* g1 = d_cwA1 + (size_t)(stage * NKC + kc) * 2048;
        const __nv_bfloat16* g2 = d_cwA2 + (size_t)(stage * NKC + kc) * 2048;
        uint32_t d1 = sb + s * CSTAGE;
        uint32_t d2 = d1 + 5120;
        int row = tid >> 2, sg = tid & 3;
        cpasync16(d1 + row * ROWB + sg * 16, g1 + row * 32 + sg * 8);
        cpasync16(d2 + row * ROWB + sg * 16, g2 + row * 32 + sg * 8);
        cp_commit();
    };
    float4 bq[4];
    auto b_issue = [&](int kc) {
        float4 z = make_float4(0.f, 0.f, 0.f, 0.f);
        bool inb = (p0 + px0) < hw;
#pragma unroll
        for (int u = 0; u < 4; ++u) {
            const float* r = chanp(kc * 32 + c0l + u);
            bq[u] = (r && inb) ? __ldg((const float4*)(r + px0)) : z;
        }
    };
    auto b_store = [&](int s) {
        uint32_t b1 = sb + s * CSTAGE + 10240;
        uint32_t b2 = b1 + 10240;
#pragma unroll
        for (int i = 0; i < 4; ++i) {
            uint32_t h[4], l[4];
#pragma unroll
            for (int u = 0; u < 4; ++u)
                bf16_split(((const float*)&bq[u])[i], h[u], l[u]);
            uint32_t hp0 = h[0] | (h[1] << 16), hp1 = h[2] | (h[3] << 16);
            uint32_t lp0 = l[0] | (l[1] << 16), lp1 = l[2] | (l[3] << 16);
            uint32_t off = (uint32_t)(px0 + i) * ROWB + c0l * 2;
            asm volatile("st.shared.v2.b32 [%0], {%1, %2};"
                         :: "r"(b1 + off), "r"(hp0), "r"(hp1) : "memory");
            asm volatile("st.shared.v2.b32 [%0], {%1, %2};"
                         :: "r"(b2 + off), "r"(lp0), "r"(lp1) : "memory");
        }
    };

    a_issue(0, 0);
    b_issue(0);
    b_store(0);
    cp_wait<0>();
    __syncthreads();

    for (int kc = 0; kc < NKC; ++kc) {
        int s = kc & 1;
        if (kc + 1 < NKC) {
            a_issue(kc + 1, s ^ 1);
            b_issue(kc + 1);
        }
        uint32_t A1b = sb + s * CSTAGE;
        uint32_t A2b = A1b + 5120;
        uint32_t B1b = A1b + 10240;
        uint32_t B2b = A1b + 20480;
#pragma unroll
        for (int ks = 0; ks < 2; ++ks) {
            uint32_t koff = ks * 32;
            uint32_t aoff = (uint32_t)(wm * 32 + a_row_l) * ROWB + koff + a_kadd;
            uint32_t boff0 = (uint32_t)(wn * 32 + b_row_l) * ROWB + koff + b_kadd;
            uint32_t boff1 = boff0 + 16 * ROWB;
            uint32_t av[8], bv1[8], bv2[8];
            ldsm_x4(bv1, B1b + boff0);
            ldsm_x4(bv1 + 4, B1b + boff1);
#pragma unroll
            for (int mf = 0; mf < 2; ++mf)
                ldsm_x4(av + mf * 4, A1b + aoff + mf * 16 * ROWB);
#pragma unroll
            for (int mf = 0; mf < 2; ++mf)
#pragma unroll
                for (int nf = 0; nf < 4; ++nf)
                    mma_bf16(acc[mf][nf], av + mf * 4, bv1 + nf * 2);
            ldsm_x4(bv2, B2b + boff0);
            ldsm_x4(bv2 + 4, B2b + boff1);
#pragma unroll
            for (int mf = 0; mf < 2; ++mf)
#pragma unroll
                for (int nf = 0; nf < 4; ++nf)
                    mma_bf16(acc[mf][nf], av + mf * 4, bv2 + nf * 2);
#pragma unroll
            for (int mf = 0; mf < 2; ++mf)
                ldsm_x4(av + mf * 4, A2b + aoff + mf * 16 * ROWB);
#pragma unroll
            for (int mf = 0; mf < 2; ++mf)
#pragma unroll
                for (int nf = 0; nf < 4; ++nf)
                    mma_bf16(acc[mf][nf], av + mf * 4, bv1 + nf * 2);
        }
        if (kc + 1 < NKC) {
            b_store(s ^ 1);
            cp_wait<0>();
        }
        __syncthreads();
    }

#pragma unroll
    for (int mf = 0; mf < 2; ++mf) {
        int row0 = wm * 32 + mf * 16 + (lane >> 2);
        int row1 = row0 + 8;
        float bias0 = __ldg(&cb[row0]);
        float bias1 = __ldg(&cb[row1]);
        float* ob0 = comp + ((size_t)b * CC + row0) * hw;
        float* ob1 = comp + ((size_t)b * CC + row1) * hw;
        int colb = wn * 32 + (lane & 3) * 2;
#pragma unroll
        for (int nf = 0; nf < 4; ++nf) {
            int col = p0 + colb + nf * 8;
            if (col < hw) {
                *(float2*)(ob0 + col) = make_float2(acc[mf][nf][0] + bias0,
                                                    acc[mf][nf][1] + bias0);
                *(float2*)(ob1 + col) = make_float2(acc[mf][nf][2] + bias1,
                                                    acc[mf][nf][3] + bias1);
            }
        }
    }
}

// ---------------- mask + softmax + pixel-shuffle fused ----------------
__global__ __launch_bounds__(256) void mask_kernel(const float* __restrict__ comp,
                                                   const float* __restrict__ ew,
                                                   const float* __restrict__ eb,
                                                   float* __restrict__ wt, int h) {
    extern __shared__ float sE[]; // [CC][9][36]
    int tid = threadIdx.x;
    for (int i = tid; i < CC * 9 * 36; i += 256) {
        int m = i % 36;
        int ck = i / 36;
        int k = ck % 9;
        int c = ck / 9;
        sE[i] = ew[(m * CC + c) * 9 + k];
    }
    __syncthreads();
    int hw = h * h;
    int pix = blockIdx.x * 256 + tid;
    int b = blockIdx.y;
    if (pix >= hw) return;
    int i = pix / h, j = pix % h;

    unsigned long long acc[18];
#pragma unroll
    for (int p = 0; p < 18; ++p)
        acc[p] = pack2(__ldg(&eb[2 * p]), __ldg(&eb[2 * p + 1]));

    int offs[9];
    bool val[9];
#pragma unroll
    for (int k = 0; k < 9; ++k) {
        int di = k / 3 - 1, dj = k % 3 - 1;
        int ii = i + di, jj = j + dj;
        val[k] = (ii >= 0) && (ii < h) && (jj >= 0) && (jj < h);
        offs[k] = val[k] ? (ii * h + jj) : 0;
    }
    const float* cp = comp + (size_t)b * CC * hw;
#pragma unroll 1
    for (int c0 = 0; c0 < CC; c0 += 4) {
        float v4[4][9];
#pragma unroll
        for (int u = 0; u < 4; ++u) {
            const float* cpu = cp + (size_t)(c0 + u) * hw;
#pragma unroll
            for (int k = 0; k < 9; ++k)
                v4[u][k] = val[k] ? cpu[offs[k]] : 0.f;
        }
#pragma unroll
        for (int u = 0; u < 4; ++u) {
#pragma unroll
            for (int k = 0; k < 9; ++k) {
                unsigned long long vv = dup2(v4[u][k]);
                const ulonglong2* w2 = (const ulonglong2*)&sE[((c0 + u) * 9 + k) * 36];
#pragma unroll
                for (int q = 0; q < 9; ++q) {
                    ulonglong2 w = w2[q];
                    acc[2 * q] = ffma2(vv, w.x, acc[2 * q]);
                    acc[2 * q + 1] = ffma2(vv, w.y, acc[2 * q + 1]);
                }
            }
        }
    }
    // fused softmax over the 9 taps of each quad member pq (channel c = 4k + pq)
    float vals[4][9];
#pragma unroll
    for (int pq = 0; pq < 4; ++pq) {
#pragma unroll
        for (int k = 0; k < 9; ++k) {
            int c = 4 * k + pq;
            vals[pq][k] = (c & 1) ? hi2(acc[c >> 1]) : lo2(acc[c >> 1]);
        }
        float mx = -1e30f;
#pragma unroll
        for (int k = 0; k < 9; ++k) mx = fmaxf(mx, vals[pq][k]);
        float s = 0.f;
#pragma unroll
        for (int k = 0; k < 9; ++k) {
            vals[pq][k] = __expf(vals[pq][k] - mx);
            s += vals[pq][k];
        }
        float inv = 1.f / s;
#pragma unroll
        for (int k = 0; k < 9; ++k) vals[pq][k] *= inv;
    }
    float* wp = wt + (((size_t)b * 9) * hw + pix) * 4;
#pragma unroll
    for (int k = 0; k < 9; ++k)
        *(float4*)(wp + (size_t)k * hw * 4) =
            make_float4(vals[0][k], vals[1][k], vals[2][k], vals[3][k]);
}

// ---------------- CARAFE reassembly: channel-split grid, one thread per low-res pixel ----------------
#define CARAFE_CH 8
#define CARAFE_NE (CARAFE_CH * 324)  // 18x18 window per channel
__global__ __launch_bounds__(256) void carafe_kernel(const float* __restrict__ src,
                                                     const float* __restrict__ wt,
                                                     float* __restrict__ out, int h,
                                                     int nt, int chans_per_block) {
    int H = 2 * h, hw = h * h, HW = H * H;
    int b = blockIdx.z;
    int tile = blockIdx.x;
    int i0 = (tile / nt) * 16;
    int j0 = (tile % nt) * 16;
    int cc0 = blockIdx.y * chans_per_block;
    int tid = threadIdx.x;
    int ti = tid >> 4, tj = tid & 15;
    int i = i0 + ti, j = j0 + tj;
    bool valid = (i < h) && (j < h);
    __shared__ float xs[2][CARAFE_CH][18][18];

    float4 w4[9];
    {
        const float4* wb = (const float4*)(wt + (((size_t)b * 9) * hw + i * h + j) * 4);
#pragma unroll
        for (int k = 0; k < 9; ++k)
            w4[k] = valid ? wb[(size_t)k * hw] : make_float4(0.f, 0.f, 0.f, 0.f);
    }

    int loff[11], sflat[11];
    bool vld[11];
    int cnt = 0;
    for (int e = tid; e < CARAFE_NE; e += 256) {
        int c = e / 324;
        int r = e % 324;
        int ii = r / 18, jj = r % 18;
        int gi = i0 - 1 + ii, gj = j0 - 1 + jj;
        bool v = (gi >= 0) && (gi < h) && (gj >= 0) && (gj < h);
        loff[cnt] = c * hw + (v ? (gi * h + gj) : 0);
        sflat[cnt] = e;
        vld[cnt] = v;
        cnt++;
    }
    const float* sbp = src + (size_t)b * DIMC * hw;
    float* ob = out + (size_t)b * DIMC * HW;
    float rv[11];
    {
        const float* sb0 = sbp + (size_t)cc0 * hw;
#pragma unroll
        for (int q = 0; q < 11; ++q)
            rv[q] = (q < cnt && vld[q]) ? __ldg(sb0 + loff[q]) : 0.f;
    }

    int I = 2 * i, J = 2 * j;
    int cc_end = cc0 + chans_per_block;
    int it = 0;
    for (int cc = cc0; cc < cc_end; cc += CARAFE_CH, ++it) {
        int buf = it & 1;
        float* xsf = &xs[buf][0][0][0];
#pragma unroll
        for (int q = 0; q < 11; ++q)
            if (q < cnt) xsf[sflat[q]] = rv[q];
        __syncthreads();
        if (cc + CARAFE_CH < cc_end) {
            const float* sbc = sbp + (size_t)(cc + CARAFE_CH) * hw;
#pragma unroll
            for (int q = 0; q < 11; ++q)
                rv[q] = (q < cnt && vld[q]) ? __ldg(sbc + loff[q]) : 0.f;
        }
#pragma unroll
        for (int c = 0; c < CARAFE_CH; ++c) {
            float a00 = 0.f, a01 = 0.f, a10 = 0.f, a11 = 0.f;
#pragma unroll
            for (int k = 0; k < 9; ++k) {
                float x = xs[buf][c][ti + k / 3][tj + k % 3];
                a00 += w4[k].x * x;
                a01 += w4[k].y * x;
                a10 += w4[k].z * x;
                a11 += w4[k].w * x;
            }
            if (valid) {
                float* o0 = ob + (size_t)(cc + c) * HW + (size_t)I * H + J;
                *(float2*)o0 = make_float2(a00, a01);
                *(float2*)(o0 + H) = make_float2(a10, a11);
            }
        }
    }
}

// ---------------- final 1x1 conv: mma.sync bf16-split (3-term) GEMM ----------------
// BM=128 (out ch), BN=128 (px), BK=32, K=416; warp grid 2x4, mf=4, nf=4.
// Stage: A1(10240) A2(10240) B1(10240) B2(10240) = 40960; 2 stages -> 2 CTA/SM.
#define STAGE_SZ 40960
#define PJ_SMEM (2 * STAGE_SZ)
__global__ __launch_bounds__(256, 2) void proj_mma_kernel(const float* __restrict__ s16,
                                                          const float* __restrict__ guid,
                                                          const float* __restrict__ pb,
                                                          float* __restrict__ out) {
    extern __shared__ char smem[];
    const uint32_t sb = smem_u32(smem);
    const int tid = threadIdx.x;
    const int wid = tid >> 5, lane = tid & 31;
    const int wm = wid >> 2, wn = wid & 3;          // warp grid 2 x 4
    const int pt = blockIdx.x, ot = blockIdx.y, b = blockIdx.z;
    const size_t NPIX = 50176;
    const size_t p0 = (size_t)pt * 128;
    const int o0 = ot * 128;

    float acc[4][4][4];
#pragma unroll
    for (int mf = 0; mf < 4; ++mf)
#pragma unroll
        for (int nf = 0; nf < 4; ++nf)
#pragma unroll
            for (int r = 0; r < 4; ++r) acc[mf][nf][r] = 0.f;

    // B fill: channel quad cq (4 ch), pixel group pg (4 px)
    const int cq = tid & 7, pg = tid >> 3;
    const int c0l = 4 * cq, px0 = pg * 4;

    const int a_row_l = lane & 15;
    const int a_kadd = (lane >> 4) << 4;
    const int b_row_l = (lane & 7) | ((lane & 16) >> 1);
    const int b_kadd = (lane & 8) << 1;

    auto chanp = [&](int c) -> const float* {
        if (c < DIMC) return s16 + ((size_t)(b * DIMC + c)) * NPIX + p0;
        if (c < CIN) return guid + ((size_t)(b * GC + (c - DIMC))) * NPIX + p0;
        return (const float*)0;
    };

    auto a_issue = [&](int kc, int s) {
        const __nv_bfloat16* g1 = d_pwA1 + (ot * NKC + kc) * 4096;
        const __nv_bfloat16* g2 = d_pwA2 + (ot * NKC + kc) * 4096;
        uint32_t d1 = sb + s * STAGE_SZ;
        uint32_t d2 = d1 + 10240;
#pragma unroll
        for (int r = 0; r < 2; ++r) {
            int seg = tid + r * 256;           // 512 segments of 16B
            int row = seg >> 2, sg = seg & 3;
            cpasync16(d1 + row * ROWB + sg * 16, g1 + row * 32 + sg * 8);
            cpasync16(d2 + row * ROWB + sg * 16, g2 + row * 32 + sg * 8);
        }
        cp_commit();
    };
    float4 bq[4];
    auto b_issue = [&](int kc) {
        float4 z = make_float4(0.f, 0.f, 0.f, 0.f);
#pragma unroll
        for (int u = 0; u < 4; ++u) {
            const float* r = chanp(kc * 32 + c0l + u);
            bq[u] = r ? __ldg((const float4*)(r + px0)) : z;
        }
    };
    auto b_store = [&](int s) {
        uint32_t b1 = sb + s * STAGE_SZ + 20480;
        uint32_t b2 = b1 + 10240;
#pragma unroll
        for (int i = 0; i < 4; ++i) {
            uint32_t h[4], l[4];
#pragma unroll
            for (int u = 0; u < 4; ++u)
                bf16_split(((const float*)&bq[u])[i], h[u], l[u]);
            uint32_t hp0 = h[0] | (h[1] << 16), hp1 = h[2] | (h[3] << 16);
            uint32_t lp0 = l[0] | (l[1] << 16), lp1 = l[2] | (l[3] << 16);
            uint32_t off = (uint32_t)(px0 + i) * ROWB + c0l * 2;
            asm volatile("st.shared.v2.b32 [%0], {%1, %2};"
                         :: "r"(b1 + off), "r"(hp0), "r"(hp1) : "memory");
            asm volatile("st.shared.v2.b32 [%0], {%1, %2};"
                         :: "r"(b2 + off), "r"(lp0), "r"(lp1) : "memory");
        }
    };

    // prefill chunk 0
    a_issue(0, 0);
    b_issue(0);
    b_store(0);
    cp_wait<0>();
    __syncthreads();

    for (int kc = 0; kc < NKC; ++kc) {
        int s = kc & 1;
        if (kc + 1 < NKC) {
            a_issue(kc + 1, s ^ 1);   // async
            b_issue(kc + 1);          // LDGs in flight during compute
        }
        uint32_t A1b = sb + s * STAGE_SZ;
        uint32_t A2b = A1b + 10240;
        uint32_t B1b = A1b + 20480;
        uint32_t B2b = A1b + 30720;
#pragma unroll
        for (int ks = 0; ks < 2; ++ks) {
            uint32_t koff = ks * 32;
            uint32_t aoff = (uint32_t)(wm * 64 + a_row_l) * ROWB + koff + a_kadd;
            uint32_t boff0 = (uint32_t)(wn * 32 + b_row_l) * ROWB + koff + b_kadd;
            uint32_t boff1 = boff0 + 16 * ROWB;
            uint32_t av[16], bv1[8], bv2[8];
            ldsm_x4(bv1, B1b + boff0);
            ldsm_x4(bv1 + 4, B1b + boff1);
#pragma unroll
            for (int mf = 0; mf < 4; ++mf)
                ldsm_x4(av + mf * 4, A1b + aoff + mf * 16 * ROWB);
#pragma unroll
            for (int mf = 0; mf < 4; ++mf)
#pragma unroll
                for (int nf = 0; nf < 4; ++nf)
                    mma_bf16(acc[mf][nf], av + mf * 4, bv1 + nf * 2);
            ldsm_x4(bv2, B2b + boff0);
            ldsm_x4(bv2 + 4, B2b + boff1);
#pragma unroll
            for (int mf = 0; mf < 4; ++mf)
#pragma unroll
                for (int nf = 0; nf < 4; ++nf)
                    mma_bf16(acc[mf][nf], av + mf * 4, bv2 + nf * 2);
#pragma unroll
            for (int mf = 0; mf < 4; ++mf)
                ldsm_x4(av + mf * 4, A2b + aoff + mf * 16 * ROWB);
#pragma unroll
            for (int mf = 0; mf < 4; ++mf)
#pragma unroll
                for (int nf = 0; nf < 4; ++nf)
                    mma_bf16(acc[mf][nf], av + mf * 4, bv1 + nf * 2);
        }
        if (kc + 1 < NKC) {
            b_store(s ^ 1);
            cp_wait<0>();
        }
        __syncthreads();
    }

    // ---- epilogue ----
#pragma unroll
    for (int mf = 0; mf < 4; ++mf) {
        int row0 = o0 + wm * 64 + mf * 16 + (lane >> 2);
        int row1 = row0 + 8;
        float bias0 = __ldg(&pb[row0]);
        float bias1 = __ldg(&pb[row1]);
        float* ob0 = out + ((size_t)(b * DIMC + row0)) * NPIX + p0 + wn * 32 + (lane & 3) * 2;
        float* ob1 = out + ((size_t)(b * DIMC + row1)) * NPIX + p0 + wn * 32 + (lane & 3) * 2;
#pragma unroll
        for (int nf = 0; nf < 4; ++nf) {
            *(float2*)(ob0 + nf * 8) = make_float2(acc[mf][nf][0] + bias0,
                                                   acc[mf][nf][1] + bias0);
            *(float2*)(ob1 + nf * 8) = make_float2(acc[mf][nf][2] + bias1,
                                                   acc[mf][nf][3] + bias1);
        }
    }
}

// ---------------- driver ----------------
extern "C" void kernel_launch(void* const* d_in, const int* in_sizes, int n_in,
                              void* d_out, int out_size) {
    (void)in_sizes; (void)n_in; (void)out_size;
    const float* source = (const float*)d_in[0];
    const float* guid = (const float*)d_in[1];
    const float* proj_w = (const float*)d_in[18];
    const float* proj_b = (const float*)d_in[19];

    float *s2, *s4, *s8, *s16, *gresA, *comp, *wtb;
    cudaGetSymbolAddress((void**)&s2, d_s2);
    cudaGetSymbolAddress((void**)&s4, d_s4);
    cudaGetSymbolAddress((void**)&s8, d_s8);
    cudaGetSymbolAddress((void**)&s16, d_s16);
    cudaGetSymbolAddress((void**)&gresA, d_gresA);
    cudaGetSymbolAddress((void**)&comp, d_comp);
    cudaGetSymbolAddress((void**)&wtb, d_wt);

    cudaFuncSetAttribute(mask_kernel, cudaFuncAttributeMaxDynamicSharedMemorySize,
                         CC * 9 * 36 * 4);
    cudaFuncSetAttribute(comp_mma_kernel, cudaFuncAttributeMaxDynamicSharedMemorySize,
                         CSMEM);
    cudaFuncSetAttribute(proj_mma_kernel, cudaFuncAttributeMaxDynamicSharedMemorySize,
                         PJ_SMEM);

    // fused prep: proj weight pack + comp weight packs + all resizes
    prep_kernel<<<(PREP_N + 255) / 256, 256>>>(
        proj_w, (const float*)d_in[2], (const float*)d_in[6],
        (const float*)d_in[10], (const float*)d_in[14], guid, gresA);

    const float* cur = source;
    float* outs[4] = {s2, s4, s8, s16};
    const int hs[4] = {14, 28, 56, 112};
    const int goff[4] = {GRES_OFF0, GRES_OFF1, GRES_OFF2, GRES_OFF3};
    const int nchg[4] = {48, 12, 4, 2};   // channel groups per stage (DIMC/(8*nchg) chunks each)
    for (int s = 0; s < 4; ++s) {
        int h = hs[s], hw = h * h;
        const float* cb = (const float*)d_in[3 + 4 * s];
        const float* ew = (const float*)d_in[4 + 4 * s];
        const float* eb = (const float*)d_in[5 + 4 * s];
        comp_mma_kernel<<<dim3((hw + 127) / 128, NB), 256, CSMEM>>>(cur, gresA + goff[s],
                                                                    cb, comp, hw, s);
        mask_kernel<<<dim3((hw + 255) / 256, NB), 256, CC * 9 * 36 * 4>>>(comp, ew, eb,
                                                                          wtb, h);
        int nt = (h + 15) / 16;
        int cpb = DIMC / nchg[s];
        carafe_kernel<<<dim3(nt * nt, nchg[s], NB), 256>>>(cur, wtb, outs[s], h, nt, cpb);
        cur = outs[s];
    }
    proj_mma_kernel<<<dim3(392, 3, NB), 256, PJ_SMEM>>>(s16, guid, proj_b, (float*)d_out);
}